// round 3
// baseline (speedup 1.0000x reference)
#include <cuda_runtime.h>

#define D_MODEL 32
#define SEQ 128

typedef unsigned long long u64;

static __device__ __forceinline__ u64 pack2(float lo, float hi) {
    u64 r; asm("mov.b64 %0, {%1, %2};" : "=l"(r) : "f"(lo), "f"(hi)); return r;
}
static __device__ __forceinline__ float2 unpack2(u64 v) {
    float2 f; asm("mov.b64 {%0, %1}, %2;" : "=f"(f.x), "=f"(f.y) : "l"(v)); return f;
}
static __device__ __forceinline__ u64 fma2(u64 a, u64 b, u64 c) {
    u64 r; asm("fma.rn.f32x2 %0, %1, %2, %3;" : "=l"(r) : "l"(a), "l"(b), "l"(c)); return r;
}
static __device__ __forceinline__ u64 add2(u64 a, u64 b) {
    u64 r; asm("add.rn.f32x2 %0, %1, %2;" : "=l"(r) : "l"(a), "l"(b)); return r;
}
static __device__ __forceinline__ u64 mul2(u64 a, u64 b) {
    u64 r; asm("mul.rn.f32x2 %0, %1, %2;" : "=l"(r) : "l"(a), "l"(b)); return r;
}
static __device__ __forceinline__ float ex2f(float z) {
    float r; asm("ex2.approx.f32 %0, %1;" : "=f"(r) : "f"(z)); return r;
}
// t = z + 12582912.0f carries round(z) in its low mantissa bits; splice into an exponent.
static __device__ __forceinline__ float scale_from_t(float t) {
    int i = __float_as_int(t);
    return __int_as_float((i << 23) + 0x3f800000);
}

__global__ __launch_bounds__(SEQ) void attn_fused_kernel(
    const float* __restrict__ x,
    const float* __restrict__ Wt, const float* __restrict__ bt,
    const float* __restrict__ Wq, const float* __restrict__ bq,
    const float* __restrict__ Wk,
    const float* __restrict__ Wv, const float* __restrict__ bv,
    const float* __restrict__ Wo, const float* __restrict__ bo,
    float* __restrict__ out)
{
    __shared__ float sx[SEQ];
    __shared__ float smx[4], smn[4], ssum[4];
    __shared__ float sparams[4];

    const int b = blockIdx.x;
    const int t = threadIdx.x;
    const int w = t >> 5, l = t & 31;

    float xv = x[(size_t)b * SEQ + t];
    sx[t] = xv;

    // block max/min of x (softmax stabilization)
    float mx = xv, mn = xv;
#pragma unroll
    for (int o = 16; o > 0; o >>= 1) {
        mx = fmaxf(mx, __shfl_xor_sync(0xffffffffu, mx, o));
        mn = fminf(mn, __shfl_xor_sync(0xffffffffu, mn, o));
    }
    if (l == 0) { smx[w] = mx; smn[w] = mn; }

    // warp 0: collapse all weights into 4 scalars (redundant per CTA; L2-resident)
    if (w == 0) {
        float qa = 0.f, qb = 0.f, ka = 0.f, va = 0.f, vb = 0.f;
#pragma unroll
        for (int d = 0; d < D_MODEL; d++) {
            float wt  = __ldg(&Wt[d]);
            float btd = __ldg(&bt[d]);
            float wq  = __ldg(&Wq[d * D_MODEL + l]);
            float wk  = __ldg(&Wk[d * D_MODEL + l]);
            float wv  = __ldg(&Wv[d * D_MODEL + l]);
            qa = fmaf(wt,  wq, qa);
            qb = fmaf(btd, wq, qb);
            ka = fmaf(wt,  wk, ka);
            va = fmaf(wt,  wv, va);
            vb = fmaf(btd, wv, vb);
        }
        qb += __ldg(&bq[l]);
        vb += __ldg(&bv[l]);
        float wo = __ldg(&Wo[l]);

        float A  = qa * ka;
        float C  = qb * ka;
        float al = va * wo;
        float be = vb * wo;
#pragma unroll
        for (int o = 16; o > 0; o >>= 1) {
            A  += __shfl_xor_sync(0xffffffffu, A,  o);
            C  += __shfl_xor_sync(0xffffffffu, C,  o);
            al += __shfl_xor_sync(0xffffffffu, al, o);
            be += __shfl_xor_sync(0xffffffffu, be, o);
        }
        if (l == 0) {
            const float L2E = 1.4426950408889634f;
            float inv = L2E / sqrtf((float)D_MODEL);   // fold 1/sqrt(D) and log2(e)
            sparams[0] = A * inv;
            sparams[1] = C * inv;
            sparams[2] = al;
            sparams[3] = be + __ldg(&bo[0]);
        }
    }
    __syncthreads();

    mx = fmaxf(fmaxf(smx[0], smx[1]), fmaxf(smx[2], smx[3]));
    mn = fminf(fminf(smn[0], smn[1]), fminf(smn[2], smn[3]));

    const float Au = sparams[0], Cu = sparams[1];
    const float u = fmaf(Au, xv, Cu);                 // log2-domain logit slope
    const float lmax = (u >= 0.f) ? u * mx : u * mn;  // max_k(u*x_k)
    const float v = -lmax;

    const u64 u2   = pack2(u, u);
    const u64 v2   = pack2(v, v);
    const float MAGIC = 12582912.0f;                  // 1.5 * 2^23
    const u64 M2   = pack2(MAGIC, MAGIC);
    const u64 MN2  = pack2(-MAGIC, -MAGIC);
    const u64 NEG1 = pack2(-1.0f, -1.0f);
    const u64 PC4  = pack2(0.0096181291f, 0.0096181291f);  // ln2^4/24
    const u64 PC3  = pack2(0.0555041087f, 0.0555041087f);  // ln2^3/6
    const u64 PC2  = pack2(0.2402265070f, 0.2402265070f);  // ln2^2/2
    const u64 PC1  = pack2(0.6931471806f, 0.6931471806f);  // ln2
    const u64 ONE2 = pack2(1.0f, 1.0f);

    u64 numA = 0ull, numB = 0ull, denA = 0ull, denB = 0ull;
    const float4* sx4 = reinterpret_cast<const float4*>(sx);

    // 4 blocks of 32 elems = 16 pairs each: 11 pairs via MUFU.EX2, 5 via FMA-pipe poly.
#pragma unroll 1
    for (int blk = 0; blk < 4; blk++) {
#pragma unroll
        for (int j = 0; j < 8; j++) {
            float4 q4 = sx4[blk * 8 + j];
#pragma unroll
            for (int h = 0; h < 2; h++) {
                float xa = (h == 0) ? q4.x : q4.z;
                float xb = (h == 0) ? q4.y : q4.w;
                int pairIdx = 2 * j + h;              // compile-time after unroll
                u64 x2 = pack2(xa, xb);
                u64 z2 = fma2(u2, x2, v2);            // z = u*x + v  (<= 0)
                u64 e2;
                if (pairIdx < 11) {
                    float2 z = unpack2(z2);
                    e2 = pack2(ex2f(z.x), ex2f(z.y));
                } else {
                    float2 z = unpack2(z2);
                    z.x = fmaxf(z.x, -124.0f);
                    z.y = fmaxf(z.y, -124.0f);
                    u64 zc = pack2(z.x, z.y);
                    u64 t2 = add2(zc, M2);            // low bits of t hold n = round(z)
                    u64 g2 = add2(t2, MN2);           // g = n (exact)
                    u64 f2 = fma2(g2, NEG1, zc);      // f = z - n, in [-0.5, 0.5]
                    u64 p2 = fma2(PC4, f2, PC3);
                    p2 = fma2(p2, f2, PC2);
                    p2 = fma2(p2, f2, PC1);
                    p2 = fma2(p2, f2, ONE2);          // 2^f (deg-4 Taylor)
                    float2 tt = unpack2(t2);
                    u64 s2 = pack2(scale_from_t(tt.x), scale_from_t(tt.y)); // 2^n
                    e2 = mul2(p2, s2);
                }
                if (h == 0) { denA = add2(denA, e2); numA = fma2(e2, x2, numA); }
                else        { denB = add2(denB, e2); numB = fma2(e2, x2, numB); }
            }
        }
    }

    u64 den2 = add2(denA, denB);
    u64 num2 = add2(numA, numB);
    float2 dn = unpack2(den2), nm = unpack2(num2);
    float m = __fdividef(nm.x + nm.y, dn.x + dn.y);   // softmax-weighted mean of x

#pragma unroll
    for (int o = 16; o > 0; o >>= 1)
        m += __shfl_xor_sync(0xffffffffu, m, o);
    if (l == 0) ssum[w] = m;
    __syncthreads();
    if (t == 0) {
        float s = (ssum[0] + ssum[1] + ssum[2] + ssum[3]) * (1.0f / (float)SEQ);
        out[b] = fmaf(sparams[2], s, sparams[3]);
    }
}

extern "C" void kernel_launch(void* const* d_in, const int* in_sizes, int n_in,
                              void* d_out, int out_size) {
    const float* x  = (const float*)d_in[0];
    const float* Wt = (const float*)d_in[1];
    const float* bt = (const float*)d_in[2];
    const float* Wq = (const float*)d_in[3];
    const float* bq = (const float*)d_in[4];
    const float* Wk = (const float*)d_in[5];
    const float* bv = (const float*)d_in[8];
    const float* Wv = (const float*)d_in[7];
    const float* Wo = (const float*)d_in[9];
    const float* bo = (const float*)d_in[10];
    float* out = (float*)d_out;

    const int B = in_sizes[0] / SEQ;

    attn_fused_kernel<<<B, SEQ>>>(x, Wt, bt, Wq, bq, Wk, Wv, bv, Wo, bo, out);
}

// round 7
// speedup vs baseline: 1.5866x; 1.5866x over previous
#include <cuda_runtime.h>
#include <cuda_fp16.h>

#define D_MODEL 32
#define SEQ 128

static __device__ __forceinline__ __half2 h2ex2(__half2 a) {
    unsigned int ua = *reinterpret_cast<unsigned int*>(&a);
    unsigned int ur;
    asm("ex2.approx.f16x2 %0, %1;" : "=r"(ur) : "r"(ua));
    return *reinterpret_cast<__half2*>(&ur);
}

__global__ __launch_bounds__(SEQ) void attn_fused_kernel(
    const float* __restrict__ x,
    const float* __restrict__ Wt, const float* __restrict__ bt,
    const float* __restrict__ Wq, const float* __restrict__ bq,
    const float* __restrict__ Wk,
    const float* __restrict__ Wv, const float* __restrict__ bv,
    const float* __restrict__ Wo, const float* __restrict__ bo,
    float* __restrict__ out)
{
    __shared__ float sx[SEQ];
    __shared__ unsigned int sxh[SEQ / 2];   // f16x2 pairs: lo = even index
    __shared__ float smx[4], smn[4], ssum[4];
    __shared__ float sparams[4];

    const int b = blockIdx.x;
    const int t = threadIdx.x;
    const int w = t >> 5, l = t & 31;

    float xv = x[(size_t)b * SEQ + t];
    sx[t] = xv;

    // fp16 copy of x, paired (even,odd): even lanes store {x_t, x_{t+1}}
    float xnb = __shfl_xor_sync(0xffffffffu, xv, 1);
    if ((t & 1) == 0) {
        __half2 hp = __floats2half2_rn(xv, xnb);
        sxh[t >> 1] = *reinterpret_cast<unsigned int*>(&hp);
    }

    // block max/min of x (softmax stabilization)
    float mx = xv, mn = xv;
#pragma unroll
    for (int o = 16; o > 0; o >>= 1) {
        mx = fmaxf(mx, __shfl_xor_sync(0xffffffffu, mx, o));
        mn = fminf(mn, __shfl_xor_sync(0xffffffffu, mn, o));
    }
    if (l == 0) { smx[w] = mx; smn[w] = mn; }

    // warp 0: collapse all weights into 4 scalars (L2-resident loads)
    if (w == 0) {
        float qa = 0.f, qb = 0.f, ka = 0.f, va = 0.f, vb = 0.f;
#pragma unroll
        for (int d = 0; d < D_MODEL; d++) {
            float wt  = __ldg(&Wt[d]);
            float btd = __ldg(&bt[d]);
            float wq  = __ldg(&Wq[d * D_MODEL + l]);
            float wk  = __ldg(&Wk[d * D_MODEL + l]);
            float wv  = __ldg(&Wv[d * D_MODEL + l]);
            qa = fmaf(wt,  wq, qa);
            qb = fmaf(btd, wq, qb);
            ka = fmaf(wt,  wk, ka);
            va = fmaf(wt,  wv, va);
            vb = fmaf(btd, wv, vb);
        }
        qb += __ldg(&bq[l]);
        vb += __ldg(&bv[l]);
        float wo = __ldg(&Wo[l]);

        float A  = qa * ka;
        float C  = qb * ka;
        float al = va * wo;
        float be = vb * wo;
#pragma unroll
        for (int o = 16; o > 0; o >>= 1) {
            A  += __shfl_xor_sync(0xffffffffu, A,  o);
            C  += __shfl_xor_sync(0xffffffffu, C,  o);
            al += __shfl_xor_sync(0xffffffffu, al, o);
            be += __shfl_xor_sync(0xffffffffu, be, o);
        }
        if (l == 0) {
            const float L2E = 1.4426950408889634f;
            float inv = L2E / sqrtf((float)D_MODEL);  // fold 1/sqrt(D) and log2(e)
            sparams[0] = A * inv;
            sparams[1] = C * inv;
            sparams[2] = al;
            sparams[3] = be + __ldg(&bo[0]);
        }
    }
    __syncthreads();

    mx = fmaxf(fmaxf(smx[0], smx[1]), fmaxf(smx[2], smx[3]));
    mn = fminf(fminf(smn[0], smn[1]), fminf(smn[2], smn[3]));

    const float u = fmaf(sparams[0], xv, sparams[1]);  // log2-domain logit slope
    const float v = -((u >= 0.f) ? u * mx : u * mn);   // -max_k(u*x_k); z <= 0

    const float4*  sx4 = reinterpret_cast<const float4*>(sx);
    const uint2*   sh2 = reinterpret_cast<const uint2*>(sxh);  // 4 elems each

    float num_f = 0.f, den_f = 0.f;
#pragma unroll 1
    for (int blk = 0; blk < 4; blk++) {
        __half2 nA = __float2half2_rn(0.f), nB = __float2half2_rn(0.f);
        __half2 dA = __float2half2_rn(0.f), dB = __float2half2_rn(0.f);
#pragma unroll
        for (int j = 0; j < 8; j++) {
            int p = blk * 8 + j;
            float4 q4 = sx4[p];
            uint2  hx = sh2[p];
            __half2 xh0 = *reinterpret_cast<__half2*>(&hx.x);  // elems 4p, 4p+1
            __half2 xh1 = *reinterpret_cast<__half2*>(&hx.y);  // elems 4p+2, 4p+3
            float z0 = fmaf(u, q4.x, v);
            float z1 = fmaf(u, q4.y, v);
            float z2 = fmaf(u, q4.z, v);
            float z3 = fmaf(u, q4.w, v);
            __half2 e0 = h2ex2(__floats2half2_rn(z0, z1));
            __half2 e1 = h2ex2(__floats2half2_rn(z2, z3));
            nA = __hfma2(e0, xh0, nA);  dA = __hadd2(dA, e0);
            nB = __hfma2(e1, xh1, nB);  dB = __hadd2(dB, e1);
        }
        float2 dsum = __half22float2(__hadd2(dA, dB));
        float2 nsum = __half22float2(__hadd2(nA, nB));
        den_f += dsum.x + dsum.y;
        num_f += nsum.x + nsum.y;
    }

    float m = __fdividef(num_f, den_f);  // softmax-weighted mean of x

#pragma unroll
    for (int o = 16; o > 0; o >>= 1)
        m += __shfl_xor_sync(0xffffffffu, m, o);
    if (l == 0) ssum[w] = m;
    __syncthreads();
    if (t == 0) {
        float s = (ssum[0] + ssum[1] + ssum[2] + ssum[3]) * (1.0f / (float)SEQ);
        out[b] = fmaf(sparams[2], s, sparams[3]);
    }
}

extern "C" void kernel_launch(void* const* d_in, const int* in_sizes, int n_in,
                              void* d_out, int out_size) {
    const float* x  = (const float*)d_in[0];
    const float* Wt = (const float*)d_in[1];
    const float* bt = (const float*)d_in[2];
    const float* Wq = (const float*)d_in[3];
    const float* bq = (const float*)d_in[4];
    const float* Wv = (const float*)d_in[7];
    const float* bv = (const float*)d_in[8];
    const float* Wk = (const float*)d_in[5];
    const float* Wo = (const float*)d_in[9];
    const float* bo = (const float*)d_in[10];
    float* out = (float*)d_out;

    const int B = in_sizes[0] / SEQ;

    attn_fused_kernel<<<B, SEQ>>>(x, Wt, bt, Wq, bq, Wk, Wv, bv, Wo, bo, out);
}